// round 1
// baseline (speedup 1.0000x reference)
#include <cuda_runtime.h>
#include <math.h>

#define S_LEN 4096
#define DM    1024
#define NH    16
#define NKV   4
#define HD    64
#define KV_W  (NKV*HD)   // 256

// Scratch (allocation-free rule: __device__ globals)
__device__ float g_q [S_LEN*DM];
__device__ float g_k [S_LEN*KV_W];
__device__ float g_v [S_LEN*KV_W];
__device__ float g_ao[S_LEN*DM];

// ---------------------------------------------------------------------------
// Generic fp32 GEMM: C[M,N] = A[M,K] @ B[K,N], all row-major.
// 64x64 block tile, K-tile 16, 256 threads, 4x4 per thread.
// ---------------------------------------------------------------------------
__global__ void gemm64(const float* __restrict__ A, const float* __restrict__ B,
                       float* __restrict__ C, int M, int N, int K) {
    __shared__ float As[16*68];   // As[k][m], padded stride 68
    __shared__ float Bs[16*68];   // Bs[k][n]
    const int tid = threadIdx.x;
    const int tx = tid & 15, ty = tid >> 4;
    const int row0 = blockIdx.y << 6, col0 = blockIdx.x << 6;

    float acc[4][4] = {};
    for (int kt = 0; kt < K; kt += 16) {
        #pragma unroll
        for (int r = 0; r < 4; r++) {
            int idx = tid + (r << 8);            // 0..1023
            int m  = idx >> 4, ka = idx & 15;    // A tile: 64 rows x 16 k
            As[ka*68 + m] = A[(size_t)(row0 + m)*K + kt + ka];
            int kb = idx >> 6, n = idx & 63;     // B tile: 16 k x 64 n
            Bs[kb*68 + n] = B[(size_t)(kt + kb)*N + col0 + n];
        }
        __syncthreads();
        #pragma unroll
        for (int kk = 0; kk < 16; kk++) {
            float4 a4 = *(const float4*)&As[kk*68 + (ty << 2)];
            float4 b4 = *(const float4*)&Bs[kk*68 + (tx << 2)];
            float av[4] = {a4.x, a4.y, a4.z, a4.w};
            float bv[4] = {b4.x, b4.y, b4.z, b4.w};
            #pragma unroll
            for (int i = 0; i < 4; i++)
                #pragma unroll
                for (int j = 0; j < 4; j++)
                    acc[i][j] += av[i] * bv[j];
        }
        __syncthreads();
    }
    #pragma unroll
    for (int i = 0; i < 4; i++) {
        float4 o = make_float4(acc[i][0], acc[i][1], acc[i][2], acc[i][3]);
        *(float4*)&C[(size_t)(row0 + (ty << 2) + i)*N + col0 + (tx << 2)] = o;
    }
}

// ---------------------------------------------------------------------------
// RoPE in-place on q (16 heads) and k (4 heads). One thread per (s, head, i<32).
// Matches reference: f32 inv_freq, f32 angle = s*inv_freq, f32 cos/sin.
// ---------------------------------------------------------------------------
__global__ void rope_kernel(float* __restrict__ q, float* __restrict__ k) {
    int idx = blockIdx.x * blockDim.x + threadIdx.x;
    const int total = S_LEN * (NH + NKV) * 32;
    if (idx >= total) return;
    int half = idx & 31;
    int rest = idx >> 5;
    int head = rest % (NH + NKV);
    int s    = rest / (NH + NKV);
    // inv_freq = 10000^(-half/32) ; compute in double, round to f32 (ref is f32)
    float inv = (float)exp((double)half * (-9.210340371976184 / 32.0));
    float ang = (float)s * inv;
    float c = cosf(ang), sn = sinf(ang);
    float* base;
    if (head < NH) base = q + (size_t)s*DM   + head*HD;
    else           base = k + (size_t)s*KV_W + (head - NH)*HD;
    float t1 = base[half];
    float t2 = base[half + 32];
    base[half]      = t1 * c - t2 * sn;
    base[half + 32] = t1 * sn + t2 * c;
}

// ---------------------------------------------------------------------------
// Flash-style attention. Grid: (S/64 q-blocks, 16 heads). 256 threads.
// Per CTA: Q tile 64x64 (smem, transposed), stream K/V in 64-key tiles,
// online softmax, P staged via smem for the PV GEMM.
// ---------------------------------------------------------------------------
__global__ void attn_kernel(const float* __restrict__ q, const float* __restrict__ k,
                            const float* __restrict__ v, float* __restrict__ out) {
    extern __shared__ float sm[];
    float* Qt = sm;               // [d][row]  64 x 68
    float* Kt = Qt + 64*68;       // [d][key]  64 x 68
    float* Vs = Kt + 64*68;       // [key][d]  64 x 68
    float* Pt = Vs + 64*68;       // [key][row]64 x 68

    const int tid = threadIdx.x;
    const int tx = tid & 15, ty = tid >> 4;
    const int h  = blockIdx.y;
    const int kh = h >> 2;               // GQA: kv head = h / 4
    const int q0 = blockIdx.x << 6;
    const float scale = 0.125f;          // 1/sqrt(64)

    // Load Q tile transposed: Qt[d][row]
    #pragma unroll
    for (int r = 0; r < 4; r++) {
        int idx = tid + (r << 8);        // float4 units, 0..1023
        int row = idx >> 4;
        int d4  = idx & 15;
        float4 val = *(const float4*)&q[(size_t)(q0 + row)*DM + h*HD + (d4 << 2)];
        Qt[(d4*4 + 0)*68 + row] = val.x;
        Qt[(d4*4 + 1)*68 + row] = val.y;
        Qt[(d4*4 + 2)*68 + row] = val.z;
        Qt[(d4*4 + 3)*68 + row] = val.w;
    }

    float m_i[4], l_i[4], acc[4][4];
    #pragma unroll
    for (int i = 0; i < 4; i++) {
        m_i[i] = -1e30f; l_i[i] = 0.f;
        #pragma unroll
        for (int j = 0; j < 4; j++) acc[i][j] = 0.f;
    }

    for (int kt = 0; kt < S_LEN; kt += 64) {
        __syncthreads();  // protects Kt/Vs/Pt from previous iteration readers; Q visible
        // Load K tile (transposed) and V tile
        #pragma unroll
        for (int r = 0; r < 4; r++) {
            int idx = tid + (r << 8);
            int key = idx >> 4;
            int d4  = idx & 15;
            float4 kv = *(const float4*)&k[(size_t)(kt + key)*KV_W + kh*HD + (d4 << 2)];
            Kt[(d4*4 + 0)*68 + key] = kv.x;
            Kt[(d4*4 + 1)*68 + key] = kv.y;
            Kt[(d4*4 + 2)*68 + key] = kv.z;
            Kt[(d4*4 + 3)*68 + key] = kv.w;
            float4 vv = *(const float4*)&v[(size_t)(kt + key)*KV_W + kh*HD + (d4 << 2)];
            *(float4*)&Vs[key*68 + (d4 << 2)] = vv;
        }
        __syncthreads();

        // S = Q @ K^T  (thread owns rows ty*4.., keys tx*4..)
        float sfr[4][4] = {};
        #pragma unroll 16
        for (int kk = 0; kk < 64; kk++) {
            float4 a4 = *(const float4*)&Qt[kk*68 + (ty << 2)];
            float4 b4 = *(const float4*)&Kt[kk*68 + (tx << 2)];
            float av[4] = {a4.x, a4.y, a4.z, a4.w};
            float bv[4] = {b4.x, b4.y, b4.z, b4.w};
            #pragma unroll
            for (int i = 0; i < 4; i++)
                #pragma unroll
                for (int j = 0; j < 4; j++)
                    sfr[i][j] += av[i] * bv[j];
        }

        // Online softmax (row reductions over the 16-lane tx group)
        #pragma unroll
        for (int i = 0; i < 4; i++) {
            float mx = sfr[i][0];
            #pragma unroll
            for (int j = 1; j < 4; j++) mx = fmaxf(mx, sfr[i][j]);
            mx *= scale;
            #pragma unroll
            for (int o = 8; o > 0; o >>= 1)
                mx = fmaxf(mx, __shfl_xor_sync(0xffffffffu, mx, o));
            float mnew  = fmaxf(m_i[i], mx);
            float alpha = __expf(m_i[i] - mnew);
            m_i[i] = mnew;
            float rs = 0.f;
            #pragma unroll
            for (int j = 0; j < 4; j++) {
                float p = __expf(sfr[i][j]*scale - mnew);
                sfr[i][j] = p;
                rs += p;
            }
            #pragma unroll
            for (int o = 8; o > 0; o >>= 1)
                rs += __shfl_xor_sync(0xffffffffu, rs, o);
            l_i[i] = l_i[i]*alpha + rs;
            #pragma unroll
            for (int j = 0; j < 4; j++) acc[i][j] *= alpha;
        }

        // Stage P transposed: Pt[key][row]
        #pragma unroll
        for (int i = 0; i < 4; i++)
            #pragma unroll
            for (int j = 0; j < 4; j++)
                Pt[((tx << 2) + j)*68 + (ty << 2) + i] = sfr[i][j];
        __syncthreads();

        // O += P @ V  (acc rows = q rows, cols = head dim)
        #pragma unroll 16
        for (int kk = 0; kk < 64; kk++) {
            float4 a4 = *(const float4*)&Pt[kk*68 + (ty << 2)];
            float4 b4 = *(const float4*)&Vs[kk*68 + (tx << 2)];
            float av[4] = {a4.x, a4.y, a4.z, a4.w};
            float bv[4] = {b4.x, b4.y, b4.z, b4.w};
            #pragma unroll
            for (int i = 0; i < 4; i++)
                #pragma unroll
                for (int j = 0; j < 4; j++)
                    acc[i][j] += av[i] * bv[j];
        }
    }

    // Normalize and store: out[(q0+row)*1024 + h*64 + col]
    #pragma unroll
    for (int i = 0; i < 4; i++) {
        float inv = 1.f / l_i[i];
        float4 o = make_float4(acc[i][0]*inv, acc[i][1]*inv, acc[i][2]*inv, acc[i][3]*inv);
        *(float4*)&out[(size_t)(q0 + (ty << 2) + i)*DM + h*HD + (tx << 2)] = o;
    }
}

// ---------------------------------------------------------------------------
extern "C" void kernel_launch(void* const* d_in, const int* in_sizes, int n_in,
                              void* d_out, int out_size) {
    const float* x   = (const float*)d_in[0];
    const float* w_q = (const float*)d_in[1];
    const float* w_k = (const float*)d_in[2];
    const float* w_v = (const float*)d_in[3];
    const float* w_o = (const float*)d_in[4];
    float* out = (float*)d_out;

    float *q, *k, *v, *ao;
    cudaGetSymbolAddress((void**)&q,  g_q);
    cudaGetSymbolAddress((void**)&k,  g_k);
    cudaGetSymbolAddress((void**)&v,  g_v);
    cudaGetSymbolAddress((void**)&ao, g_ao);

    const dim3 blk(256);

    // QKV projections
    gemm64<<<dim3(DM/64,   S_LEN/64), blk>>>(x, w_q, q, S_LEN, DM,   DM);
    gemm64<<<dim3(KV_W/64, S_LEN/64), blk>>>(x, w_k, k, S_LEN, KV_W, DM);
    gemm64<<<dim3(KV_W/64, S_LEN/64), blk>>>(x, w_v, v, S_LEN, KV_W, DM);

    // RoPE
    {
        int total = S_LEN * (NH + NKV) * 32;
        rope_kernel<<<(total + 255)/256, 256>>>(q, k);
    }

    // Attention
    {
        size_t smem = 4 * 64 * 68 * sizeof(float);   // 69632 B
        cudaFuncSetAttribute(attn_kernel, cudaFuncAttributeMaxDynamicSharedMemorySize,
                             (int)smem);
        attn_kernel<<<dim3(S_LEN/64, NH), blk, smem>>>(q, k, v, ao);
    }

    // Output projection
    gemm64<<<dim3(DM/64, S_LEN/64), blk>>>(ao, w_o, out, S_LEN, DM, DM);
}

// round 2
// speedup vs baseline: 1.0149x; 1.0149x over previous
#include <cuda_runtime.h>
#include <math.h>

#define S_LEN 4096
#define DM    1024
#define NH    16
#define NKV   4
#define HD    64
#define KV_W  (NKV*HD)   // 256

// Scratch (allocation-free rule: __device__ globals)
__device__ float g_q [S_LEN*DM];
__device__ float g_k [S_LEN*KV_W];
__device__ float g_v [S_LEN*KV_W];
__device__ float g_ao[S_LEN*DM];

typedef unsigned long long u64;

// ---- packed f32x2 helpers (FFMA2 path — ptxas never emits this itself) ----
__device__ __forceinline__ u64 pk2(float x, float y) {
    u64 r; asm("mov.b64 %0, {%1, %2};" : "=l"(r) : "f"(x), "f"(y)); return r;
}
__device__ __forceinline__ void upk2(u64 v, float& x, float& y) {
    asm("mov.b64 {%0, %1}, %2;" : "=f"(x), "=f"(y) : "l"(v));
}
__device__ __forceinline__ u64 ffma2(u64 a, u64 b, u64 c) {
    u64 d; asm("fma.rn.f32x2 %0, %1, %2, %3;" : "=l"(d) : "l"(a), "l"(b), "l"(c)); return d;
}
__device__ __forceinline__ u64 fmul2(u64 a, u64 b) {
    u64 d; asm("mul.rn.f32x2 %0, %1, %2;" : "=l"(d) : "l"(a), "l"(b)); return d;
}

// ---------------------------------------------------------------------------
// Generic fp32 GEMM: C[M,N] = A[M,K] @ B[K,N], all row-major.
// 64x64 block tile, K-tile 16, 256 threads, 4x4 per thread, f32x2 packed math.
// ---------------------------------------------------------------------------
__global__ void gemm64(const float* __restrict__ A, const float* __restrict__ B,
                       float* __restrict__ C, int M, int N, int K) {
    __shared__ float As[16*68];   // As[k][m], padded stride 68
    __shared__ float Bs[16*68];   // Bs[k][n]
    const int tid = threadIdx.x;
    const int tx = tid & 15, ty = tid >> 4;
    const int row0 = blockIdx.y << 6, col0 = blockIdx.x << 6;

    u64 acc2[4][2] = {};
    for (int kt = 0; kt < K; kt += 16) {
        #pragma unroll
        for (int r = 0; r < 4; r++) {
            int idx = tid + (r << 8);            // 0..1023
            int m  = idx >> 4, ka = idx & 15;    // A tile: 64 rows x 16 k
            As[ka*68 + m] = A[(size_t)(row0 + m)*K + kt + ka];
            int kb = idx >> 6, n = idx & 63;     // B tile: 16 k x 64 n
            Bs[kb*68 + n] = B[(size_t)(kt + kb)*N + col0 + n];
        }
        __syncthreads();
        #pragma unroll
        for (int kk = 0; kk < 16; kk++) {
            float4 a4 = *(const float4*)&As[kk*68 + (ty << 2)];
            ulonglong2 b2 = *(const ulonglong2*)&Bs[kk*68 + (tx << 2)];
            u64 ai[4] = {pk2(a4.x,a4.x), pk2(a4.y,a4.y), pk2(a4.z,a4.z), pk2(a4.w,a4.w)};
            #pragma unroll
            for (int i = 0; i < 4; i++) {
                acc2[i][0] = ffma2(ai[i], b2.x, acc2[i][0]);
                acc2[i][1] = ffma2(ai[i], b2.y, acc2[i][1]);
            }
        }
        __syncthreads();
    }
    #pragma unroll
    for (int i = 0; i < 4; i++) {
        float4 o;
        upk2(acc2[i][0], o.x, o.y);
        upk2(acc2[i][1], o.z, o.w);
        *(float4*)&C[(size_t)(row0 + (ty << 2) + i)*N + col0 + (tx << 2)] = o;
    }
}

// ---------------------------------------------------------------------------
// RoPE in-place on q (16 heads) and k (4 heads). One thread per (s, head, i<32).
// ---------------------------------------------------------------------------
__global__ void rope_kernel(float* __restrict__ q, float* __restrict__ k) {
    int idx = blockIdx.x * blockDim.x + threadIdx.x;
    const int total = S_LEN * (NH + NKV) * 32;
    if (idx >= total) return;
    int half = idx & 31;
    int rest = idx >> 5;
    int head = rest % (NH + NKV);
    int s    = rest / (NH + NKV);
    // inv_freq = 10000^(-half/32) = 2^(-half*log2(10000)/32), fp32 like reference
    float inv = exp2f((float)half * -0.41524101187353416f);
    float ang = (float)s * inv;
    float c, sn;
    sincosf(ang, &sn, &c);
    float* base;
    if (head < NH) base = q + (size_t)s*DM   + head*HD;
    else           base = k + (size_t)s*KV_W + (head - NH)*HD;
    float t1 = base[half];
    float t2 = base[half + 32];
    base[half]      = t1 * c - t2 * sn;
    base[half + 32] = t1 * sn + t2 * c;
}

// ---------------------------------------------------------------------------
// Flash-style attention. Grid: (S/64 q-blocks, 16 heads). 256 threads.
// f32x2 packed math in both GEMM loops.
// ---------------------------------------------------------------------------
__global__ void attn_kernel(const float* __restrict__ q, const float* __restrict__ k,
                            const float* __restrict__ v, float* __restrict__ out) {
    extern __shared__ float sm[];
    float* Qt = sm;               // [d][row]  64 x 68
    float* Kt = Qt + 64*68;       // [d][key]  64 x 68
    float* Vs = Kt + 64*68;       // [key][d]  64 x 68
    float* Pt = Vs + 64*68;       // [key][row]64 x 68

    const int tid = threadIdx.x;
    const int tx = tid & 15, ty = tid >> 4;
    const int h  = blockIdx.y;
    const int kh = h >> 2;               // GQA: kv head = h / 4
    const int q0 = blockIdx.x << 6;
    const float scale = 0.125f;          // 1/sqrt(64)

    // Load Q tile transposed: Qt[d][row]
    #pragma unroll
    for (int r = 0; r < 4; r++) {
        int idx = tid + (r << 8);        // float4 units, 0..1023
        int row = idx >> 4;
        int d4  = idx & 15;
        float4 val = *(const float4*)&q[(size_t)(q0 + row)*DM + h*HD + (d4 << 2)];
        Qt[(d4*4 + 0)*68 + row] = val.x;
        Qt[(d4*4 + 1)*68 + row] = val.y;
        Qt[(d4*4 + 2)*68 + row] = val.z;
        Qt[(d4*4 + 3)*68 + row] = val.w;
    }

    float m_i[4], l_i[4];
    u64 acc2[4][2];
    #pragma unroll
    for (int i = 0; i < 4; i++) {
        m_i[i] = -1e30f; l_i[i] = 0.f;
        acc2[i][0] = 0ull; acc2[i][1] = 0ull;
    }

    for (int kt = 0; kt < S_LEN; kt += 64) {
        __syncthreads();  // protects Kt/Vs/Pt from previous iteration readers
        // Load K tile (transposed) and V tile
        #pragma unroll
        for (int r = 0; r < 4; r++) {
            int idx = tid + (r << 8);
            int key = idx >> 4;
            int d4  = idx & 15;
            float4 kv = *(const float4*)&k[(size_t)(kt + key)*KV_W + kh*HD + (d4 << 2)];
            Kt[(d4*4 + 0)*68 + key] = kv.x;
            Kt[(d4*4 + 1)*68 + key] = kv.y;
            Kt[(d4*4 + 2)*68 + key] = kv.z;
            Kt[(d4*4 + 3)*68 + key] = kv.w;
            float4 vv = *(const float4*)&v[(size_t)(kt + key)*KV_W + kh*HD + (d4 << 2)];
            *(float4*)&Vs[key*68 + (d4 << 2)] = vv;
        }
        __syncthreads();

        // S = Q @ K^T  (thread owns rows ty*4.., keys tx*4..), packed f32x2
        u64 s2[4][2] = {};
        #pragma unroll 16
        for (int kk = 0; kk < 64; kk++) {
            float4 a4 = *(const float4*)&Qt[kk*68 + (ty << 2)];
            ulonglong2 b2 = *(const ulonglong2*)&Kt[kk*68 + (tx << 2)];
            u64 ai[4] = {pk2(a4.x,a4.x), pk2(a4.y,a4.y), pk2(a4.z,a4.z), pk2(a4.w,a4.w)};
            #pragma unroll
            for (int i = 0; i < 4; i++) {
                s2[i][0] = ffma2(ai[i], b2.x, s2[i][0]);
                s2[i][1] = ffma2(ai[i], b2.y, s2[i][1]);
            }
        }

        // Online softmax (row reductions over the 16-lane tx group)
        #pragma unroll
        for (int i = 0; i < 4; i++) {
            float sfr[4];
            upk2(s2[i][0], sfr[0], sfr[1]);
            upk2(s2[i][1], sfr[2], sfr[3]);
            float mx = fmaxf(fmaxf(sfr[0], sfr[1]), fmaxf(sfr[2], sfr[3]));
            mx *= scale;
            #pragma unroll
            for (int o = 8; o > 0; o >>= 1)
                mx = fmaxf(mx, __shfl_xor_sync(0xffffffffu, mx, o));
            float mnew  = fmaxf(m_i[i], mx);
            float alpha = __expf(m_i[i] - mnew);
            m_i[i] = mnew;
            float rs = 0.f;
            #pragma unroll
            for (int j = 0; j < 4; j++) {
                float p = __expf(sfr[j]*scale - mnew);
                sfr[j] = p;
                rs += p;
            }
            #pragma unroll
            for (int o = 8; o > 0; o >>= 1)
                rs += __shfl_xor_sync(0xffffffffu, rs, o);
            l_i[i] = l_i[i]*alpha + rs;
            u64 aa = pk2(alpha, alpha);
            acc2[i][0] = fmul2(acc2[i][0], aa);
            acc2[i][1] = fmul2(acc2[i][1], aa);
            // Stage P transposed: Pt[key][row]
            #pragma unroll
            for (int j = 0; j < 4; j++)
                Pt[((tx << 2) + j)*68 + (ty << 2) + i] = sfr[j];
        }
        __syncthreads();

        // O += P @ V  (acc rows = q rows, cols = head dim), packed f32x2
        #pragma unroll 16
        for (int kk = 0; kk < 64; kk++) {
            float4 a4 = *(const float4*)&Pt[kk*68 + (ty << 2)];
            ulonglong2 b2 = *(const ulonglong2*)&Vs[kk*68 + (tx << 2)];
            u64 ai[4] = {pk2(a4.x,a4.x), pk2(a4.y,a4.y), pk2(a4.z,a4.z), pk2(a4.w,a4.w)};
            #pragma unroll
            for (int i = 0; i < 4; i++) {
                acc2[i][0] = ffma2(ai[i], b2.x, acc2[i][0]);
                acc2[i][1] = ffma2(ai[i], b2.y, acc2[i][1]);
            }
        }
    }

    // Normalize and store: out[(q0+row)*1024 + h*64 + col]
    #pragma unroll
    for (int i = 0; i < 4; i++) {
        float inv = 1.f / l_i[i];
        float4 o;
        upk2(acc2[i][0], o.x, o.y);
        upk2(acc2[i][1], o.z, o.w);
        o.x *= inv; o.y *= inv; o.z *= inv; o.w *= inv;
        *(float4*)&out[(size_t)(q0 + (ty << 2) + i)*DM + h*HD + (tx << 2)] = o;
    }
}

// ---------------------------------------------------------------------------
extern "C" void kernel_launch(void* const* d_in, const int* in_sizes, int n_in,
                              void* d_out, int out_size) {
    const float* x   = (const float*)d_in[0];
    const float* w_q = (const float*)d_in[1];
    const float* w_k = (const float*)d_in[2];
    const float* w_v = (const float*)d_in[3];
    const float* w_o = (const float*)d_in[4];
    float* out = (float*)d_out;

    float *q, *k, *v, *ao;
    cudaGetSymbolAddress((void**)&q,  g_q);
    cudaGetSymbolAddress((void**)&k,  g_k);
    cudaGetSymbolAddress((void**)&v,  g_v);
    cudaGetSymbolAddress((void**)&ao, g_ao);

    const dim3 blk(256);

    // QKV projections
    gemm64<<<dim3(DM/64,   S_LEN/64), blk>>>(x, w_q, q, S_LEN, DM,   DM);
    gemm64<<<dim3(KV_W/64, S_LEN/64), blk>>>(x, w_k, k, S_LEN, KV_W, DM);
    gemm64<<<dim3(KV_W/64, S_LEN/64), blk>>>(x, w_v, v, S_LEN, KV_W, DM);

    // RoPE
    {
        int total = S_LEN * (NH + NKV) * 32;
        rope_kernel<<<(total + 255)/256, 256>>>(q, k);
    }

    // Attention
    {
        size_t smem = 4 * 64 * 68 * sizeof(float);   // 69632 B
        cudaFuncSetAttribute(attn_kernel, cudaFuncAttributeMaxDynamicSharedMemorySize,
                             (int)smem);
        attn_kernel<<<dim3(S_LEN/64, NH), blk, smem>>>(q, k, v, ao);
    }

    // Output projection
    gemm64<<<dim3(DM/64, S_LEN/64), blk>>>(ao, w_o, out, S_LEN, DM, DM);
}

// round 3
// speedup vs baseline: 2.9879x; 2.9441x over previous
#include <cuda_runtime.h>
#include <math.h>
#include <stdint.h>

#define S_LEN 4096
#define DM    1024
#define NH    16
#define NKV   4
#define HD    64
#define KV_W  (NKV*HD)   // 256

// Scratch (allocation-free rule: __device__ globals)
__device__ float g_q [S_LEN*DM];
__device__ float g_k [S_LEN*KV_W];
__device__ float g_v [S_LEN*KV_W];
__device__ float g_ao[S_LEN*DM];

// ---- tf32 helpers ----
__device__ __forceinline__ uint32_t f2t(float f) {
    uint32_t r; asm("cvt.rna.tf32.f32 %0, %1;" : "=r"(r) : "f"(f)); return r;
}
__device__ __forceinline__ void mma8(float* d, uint32_t a0, uint32_t a1,
                                     uint32_t a2, uint32_t a3,
                                     uint32_t b0, uint32_t b1) {
    asm volatile(
        "mma.sync.aligned.m16n8k8.row.col.f32.tf32.tf32.f32 "
        "{%0,%1,%2,%3},{%4,%5,%6,%7},{%8,%9},{%0,%1,%2,%3};"
        : "+f"(d[0]), "+f"(d[1]), "+f"(d[2]), "+f"(d[3])
        : "r"(a0), "r"(a1), "r"(a2), "r"(a3), "r"(b0), "r"(b1));
}

// ---------------------------------------------------------------------------
// TF32 MMA GEMM: C[4096, N] = A[4096,1024] @ B[1024,N], row-major fp32.
// CTA tile: 128(M) x 64(N), K-chunk 32. 256 threads = 8 warps, warp owns m16.
// ---------------------------------------------------------------------------
__global__ __launch_bounds__(256) void gemm_mma(const float* __restrict__ A,
                                                const float* __restrict__ B,
                                                float* __restrict__ C, int N) {
    __shared__ uint32_t As[128*36];   // tf32 A tile [row][k], stride 36
    __shared__ uint32_t Bs[32*72];    // tf32 B tile [k][n],  stride 72
    const int tid = threadIdx.x;
    const int w = tid >> 5, l = tid & 31, g = l >> 2, q = l & 3;
    const int row0 = blockIdx.y << 7, n0 = blockIdx.x << 6;

    float acc[8][4] = {};
    for (int kc = 0; kc < 1024; kc += 32) {
        __syncthreads();
        #pragma unroll
        for (int i = 0; i < 4; i++) {        // A: 128x32 = 1024 float4
            int u = tid + (i << 8);
            int r = u >> 3, k4 = u & 7;
            float4 a4 = *(const float4*)&A[(size_t)(row0 + r)*1024 + kc + (k4 << 2)];
            uint32_t* dst = &As[r*36 + (k4 << 2)];
            dst[0] = f2t(a4.x); dst[1] = f2t(a4.y); dst[2] = f2t(a4.z); dst[3] = f2t(a4.w);
        }
        #pragma unroll
        for (int i = 0; i < 2; i++) {        // B: 32x64 = 512 float4
            int u = tid + (i << 8);
            int kk = u >> 4, n4 = u & 15;
            float4 b4 = *(const float4*)&B[(size_t)(kc + kk)*N + n0 + (n4 << 2)];
            uint32_t* dst = &Bs[kk*72 + (n4 << 2)];
            dst[0] = f2t(b4.x); dst[1] = f2t(b4.y); dst[2] = f2t(b4.z); dst[3] = f2t(b4.w);
        }
        __syncthreads();
        #pragma unroll
        for (int ks = 0; ks < 4; ks++) {
            uint32_t a0 = As[(w*16 + g    )*36 + ks*8 + q    ];
            uint32_t a1 = As[(w*16 + g + 8)*36 + ks*8 + q    ];
            uint32_t a2 = As[(w*16 + g    )*36 + ks*8 + q + 4];
            uint32_t a3 = As[(w*16 + g + 8)*36 + ks*8 + q + 4];
            #pragma unroll
            for (int j = 0; j < 8; j++) {
                uint32_t b0 = Bs[(ks*8 + q    )*72 + j*8 + g];
                uint32_t b1 = Bs[(ks*8 + q + 4)*72 + j*8 + g];
                mma8(acc[j], a0, a1, a2, a3, b0, b1);
            }
        }
    }
    #pragma unroll
    for (int j = 0; j < 8; j++) {
        float2 lo = make_float2(acc[j][0], acc[j][1]);
        float2 hi = make_float2(acc[j][2], acc[j][3]);
        *(float2*)&C[(size_t)(row0 + w*16 + g    )*N + n0 + j*8 + 2*q] = lo;
        *(float2*)&C[(size_t)(row0 + w*16 + g + 8)*N + n0 + j*8 + 2*q] = hi;
    }
}

// ---------------------------------------------------------------------------
// RoPE in-place on q (16 heads) and k (4 heads).
// ---------------------------------------------------------------------------
__global__ void rope_kernel(float* __restrict__ q, float* __restrict__ k) {
    int idx = blockIdx.x * blockDim.x + threadIdx.x;
    const int total = S_LEN * (NH + NKV) * 32;
    if (idx >= total) return;
    int half = idx & 31;
    int rest = idx >> 5;
    int head = rest % (NH + NKV);
    int s    = rest / (NH + NKV);
    float inv = exp2f((float)half * -0.41524101187353416f);
    float ang = (float)s * inv;
    float c, sn;
    sincosf(ang, &sn, &c);
    float* base;
    if (head < NH) base = q + (size_t)s*DM   + head*HD;
    else           base = k + (size_t)s*KV_W + (head - NH)*HD;
    float t1 = base[half];
    float t2 = base[half + 32];
    base[half]      = t1 * c - t2 * sn;
    base[half + 32] = t1 * sn + t2 * c;
}

// ---------------------------------------------------------------------------
// Flash attention via tf32 MMA. Grid: (S/128, NH). 256 threads = 8 warps.
// Warp owns 16 q-rows. K/V streamed in 64-key tiles through smem.
// ---------------------------------------------------------------------------
__global__ __launch_bounds__(256) void attn_mma(const float* __restrict__ qg,
                                                const float* __restrict__ kgm,
                                                const float* __restrict__ vgm,
                                                float* __restrict__ out) {
    __shared__ uint32_t Ks[64*68];   // tf32 K tile [key][d], stride 68
    __shared__ uint32_t Vs[64*72];   // tf32 V tile [key][d], stride 72
    const int tid = threadIdx.x;
    const int w = tid >> 5, l = tid & 31, g = l >> 2, q = l & 3;
    const int h  = blockIdx.y;
    const int kh = h >> 2;
    const int q0 = blockIdx.x << 7;

    // Q fragments for this warp's 16 rows (scale 1/8 folded in, exact).
    uint32_t qf[8][4];
    const float* qb = qg + (size_t)(q0 + w*16)*DM + h*HD;
    #pragma unroll
    for (int kg = 0; kg < 8; kg++) {
        qf[kg][0] = f2t(qb[(size_t)(g    )*DM + kg*8 + q    ] * 0.125f);
        qf[kg][1] = f2t(qb[(size_t)(g + 8)*DM + kg*8 + q    ] * 0.125f);
        qf[kg][2] = f2t(qb[(size_t)(g    )*DM + kg*8 + q + 4] * 0.125f);
        qf[kg][3] = f2t(qb[(size_t)(g + 8)*DM + kg*8 + q + 4] * 0.125f);
    }

    float oacc[8][4] = {};
    float m0 = -1e30f, m1 = -1e30f, l0 = 0.f, l1 = 0.f;
    const int src1 = (l & ~3) | (q >> 1);
    const int src2 = src1 + 2;

    for (int kt = 0; kt < S_LEN; kt += 64) {
        __syncthreads();
        // Stage K and V tiles (fp32 -> tf32 at store time)
        #pragma unroll
        for (int i = 0; i < 4; i++) {
            int u = tid + (i << 8);                 // 0..1023
            int key = u >> 4, d4 = u & 15;
            size_t goff = (size_t)(kt + key)*KV_W + kh*HD + (d4 << 2);
            float4 kv = *(const float4*)&kgm[goff];
            uint32_t* dk = &Ks[key*68 + (d4 << 2)];
            dk[0] = f2t(kv.x); dk[1] = f2t(kv.y); dk[2] = f2t(kv.z); dk[3] = f2t(kv.w);
            float4 vv = *(const float4*)&vgm[goff];
            uint32_t* dv = &Vs[key*72 + (d4 << 2)];
            dv[0] = f2t(vv.x); dv[1] = f2t(vv.y); dv[2] = f2t(vv.z); dv[3] = f2t(vv.w);
        }
        __syncthreads();

        // S = Qs @ K^T : sf[j] covers keys 8j..8j+7 for rows (g, g+8)
        float sf[8][4] = {};
        #pragma unroll
        for (int kg = 0; kg < 8; kg++) {
            #pragma unroll
            for (int j = 0; j < 8; j++) {
                uint32_t b0 = Ks[(8*j + g)*68 + 8*kg + q    ];
                uint32_t b1 = Ks[(8*j + g)*68 + 8*kg + q + 4];
                mma8(sf[j], qf[kg][0], qf[kg][1], qf[kg][2], qf[kg][3], b0, b1);
            }
        }

        // Online softmax. Row0 = g, Row1 = g+8 (per quad).
        float rmax0 = -1e30f, rmax1 = -1e30f;
        #pragma unroll
        for (int j = 0; j < 8; j++) {
            rmax0 = fmaxf(rmax0, fmaxf(sf[j][0], sf[j][1]));
            rmax1 = fmaxf(rmax1, fmaxf(sf[j][2], sf[j][3]));
        }
        #pragma unroll
        for (int o = 1; o <= 2; o <<= 1) {
            rmax0 = fmaxf(rmax0, __shfl_xor_sync(0xffffffffu, rmax0, o));
            rmax1 = fmaxf(rmax1, __shfl_xor_sync(0xffffffffu, rmax1, o));
        }
        float mn0 = fmaxf(m0, rmax0), mn1 = fmaxf(m1, rmax1);
        float al0 = __expf(m0 - mn0), al1 = __expf(m1 - mn1);
        m0 = mn0; m1 = mn1;
        float rs0 = 0.f, rs1 = 0.f;
        #pragma unroll
        for (int j = 0; j < 8; j++) {
            float p0 = __expf(sf[j][0] - mn0);
            float p1 = __expf(sf[j][1] - mn0);
            float p2 = __expf(sf[j][2] - mn1);
            float p3 = __expf(sf[j][3] - mn1);
            rs0 += p0 + p1; rs1 += p2 + p3;
            sf[j][0] = __uint_as_float(f2t(p0));
            sf[j][1] = __uint_as_float(f2t(p1));
            sf[j][2] = __uint_as_float(f2t(p2));
            sf[j][3] = __uint_as_float(f2t(p3));
        }
        #pragma unroll
        for (int o = 1; o <= 2; o <<= 1) {
            rs0 += __shfl_xor_sync(0xffffffffu, rs0, o);
            rs1 += __shfl_xor_sync(0xffffffffu, rs1, o);
        }
        l0 = l0*al0 + rs0; l1 = l1*al1 + rs1;
        #pragma unroll
        for (int j = 0; j < 8; j++) {
            oacc[j][0] *= al0; oacc[j][1] *= al0;
            oacc[j][2] *= al1; oacc[j][3] *= al1;
        }

        // O += P @ V : reshape P (C-frag) -> A-frag via quad shuffles.
        #pragma unroll
        for (int j = 0; j < 8; j++) {
            uint32_t s0 = __float_as_uint(sf[j][0]);
            uint32_t s1 = __float_as_uint(sf[j][1]);
            uint32_t s2 = __float_as_uint(sf[j][2]);
            uint32_t s3 = __float_as_uint(sf[j][3]);
            uint32_t t0 = __shfl_sync(0xffffffffu, s0, src1);
            uint32_t t1 = __shfl_sync(0xffffffffu, s1, src1);
            uint32_t t2 = __shfl_sync(0xffffffffu, s2, src1);
            uint32_t t3 = __shfl_sync(0xffffffffu, s3, src1);
            uint32_t u0 = __shfl_sync(0xffffffffu, s0, src2);
            uint32_t u1 = __shfl_sync(0xffffffffu, s1, src2);
            uint32_t u2 = __shfl_sync(0xffffffffu, s2, src2);
            uint32_t u3 = __shfl_sync(0xffffffffu, s3, src2);
            uint32_t a0 = (q & 1) ? t1 : t0;
            uint32_t a1 = (q & 1) ? t3 : t2;
            uint32_t a2 = (q & 1) ? u1 : u0;
            uint32_t a3 = (q & 1) ? u3 : u2;
            #pragma unroll
            for (int n = 0; n < 8; n++) {
                uint32_t b0 = Vs[(8*j + q    )*72 + 8*n + g];
                uint32_t b1 = Vs[(8*j + q + 4)*72 + 8*n + g];
                mma8(oacc[n], a0, a1, a2, a3, b0, b1);
            }
        }
    }

    // Epilogue: normalize and write.
    float inv0 = 1.f / l0, inv1 = 1.f / l1;
    #pragma unroll
    for (int j = 0; j < 8; j++) {
        float2 lo = make_float2(oacc[j][0]*inv0, oacc[j][1]*inv0);
        float2 hi = make_float2(oacc[j][2]*inv1, oacc[j][3]*inv1);
        *(float2*)&out[(size_t)(q0 + w*16 + g    )*DM + h*HD + j*8 + 2*q] = lo;
        *(float2*)&out[(size_t)(q0 + w*16 + g + 8)*DM + h*HD + j*8 + 2*q] = hi;
    }
}

// ---------------------------------------------------------------------------
extern "C" void kernel_launch(void* const* d_in, const int* in_sizes, int n_in,
                              void* d_out, int out_size) {
    const float* x   = (const float*)d_in[0];
    const float* w_q = (const float*)d_in[1];
    const float* w_k = (const float*)d_in[2];
    const float* w_v = (const float*)d_in[3];
    const float* w_o = (const float*)d_in[4];
    float* out = (float*)d_out;

    float *q, *k, *v, *ao;
    cudaGetSymbolAddress((void**)&q,  g_q);
    cudaGetSymbolAddress((void**)&k,  g_k);
    cudaGetSymbolAddress((void**)&v,  g_v);
    cudaGetSymbolAddress((void**)&ao, g_ao);

    // Projections (tf32 MMA)
    gemm_mma<<<dim3(DM/64,   S_LEN/128), 256>>>(x, w_q, q, DM);
    gemm_mma<<<dim3(KV_W/64, S_LEN/128), 256>>>(x, w_k, k, KV_W);
    gemm_mma<<<dim3(KV_W/64, S_LEN/128), 256>>>(x, w_v, v, KV_W);

    // RoPE
    {
        int total = S_LEN * (NH + NKV) * 32;
        rope_kernel<<<(total + 255)/256, 256>>>(q, k);
    }

    // Attention (tf32 MMA flash)
    attn_mma<<<dim3(S_LEN/128, NH), 256>>>(q, k, v, ao);

    // Output projection
    gemm_mma<<<dim3(DM/64, S_LEN/128), 256>>>(ao, w_o, out, DM);
}